// round 1
// baseline (speedup 1.0000x reference)
#include <cuda_runtime.h>
#include <math.h>
#include <stdint.h>

#define NROWS 8
#define DTOT  (1u<<20)      // 1048576 columns of U
#define D1    1024
#define D2    1024
#define BB    1024
#define NBLK  4096          // DTOT / 256

// ---------------- static device scratch (allocation-free rule) ----------------
__device__ float    g_sortedA[NROWS*DTOT];   // 32 MB
__device__ float    g_sortedB[NROWS*DTOT];   // 32 MB
__device__ float    g_w[NROWS*DTOT];         // 32 MB  final quantized weights
__device__ unsigned g_ordA[DTOT];            // 4 MB (8 x 3-bit packed row ids)
__device__ unsigned g_ordB[DTOT];            // 4 MB
__device__ float    g_part[NBLK*8];          // per-block partials: 7 delta sums + 1 delta max
__device__ unsigned g_minenc, g_maxenc;      // encoded min/max of U
__device__ float    g_coef[8];               // grad_g[gid[i]] per sorted row
__device__ float    g_cnt[8];                // counts[gid[i]] per sorted row (float)
__device__ int      g_same[7];               // 1 if sorted rows i,i+1 in same group (b==0)

// ---------------- helpers ----------------
__device__ __forceinline__ unsigned fenc(float f){
    unsigned u = __float_as_uint(f);
    return (u & 0x80000000u) ? ~u : (u | 0x80000000u);   // monotone float->uint
}
__device__ __forceinline__ float fdec(unsigned u){
    unsigned v = (u & 0x80000000u) ? (u & 0x7fffffffu) : ~u;
    return __uint_as_float(v);
}

// stable compare-exchange on (value, original-row) keys
__device__ __forceinline__ void ce(float &va, int &ia, float &vb, int &ib){
    bool sw = (va > vb) || (va == vb && ia > ib);
    if (sw){ float tv=va; va=vb; vb=tv; int ti=ia; ia=ib; ib=ti; }
}
// Batcher odd-even mergesort network for 8 elements (19 CEs), all static indices
__device__ __forceinline__ void sort8(float v[8], int id[8]){
    ce(v[0],id[0],v[1],id[1]); ce(v[2],id[2],v[3],id[3]); ce(v[4],id[4],v[5],id[5]); ce(v[6],id[6],v[7],id[7]);
    ce(v[0],id[0],v[2],id[2]); ce(v[1],id[1],v[3],id[3]); ce(v[4],id[4],v[6],id[6]); ce(v[5],id[5],v[7],id[7]);
    ce(v[1],id[1],v[2],id[2]); ce(v[5],id[5],v[6],id[6]);
    ce(v[0],id[0],v[4],id[4]); ce(v[1],id[1],v[5],id[5]); ce(v[2],id[2],v[6],id[6]); ce(v[3],id[3],v[7],id[7]);
    ce(v[2],id[2],v[4],id[4]); ce(v[3],id[3],v[5],id[5]);
    ce(v[1],id[1],v[2],id[2]); ce(v[3],id[3],v[4],id[4]); ce(v[5],id[5],v[6],id[6]);
}

// block-reduce 7 delta sums + delta max into g_part[blk*8 + q]
__device__ __forceinline__ void delta_stats(const float v[8], float (*sdel)[257], int tid, int blk){
    #pragma unroll
    for (int i=0;i<7;i++) sdel[i][tid] = v[i+1]-v[i];
    float mx = 0.f;
    #pragma unroll
    for (int i=0;i<7;i++) mx = fmaxf(mx, v[i+1]-v[i]);
    sdel[7][tid] = mx;
    __syncthreads();
    for (int s=128; s; s>>=1){
        if (tid < s){
            #pragma unroll
            for (int q=0;q<8;q++){
                float a = sdel[q][tid], b = sdel[q][tid+s];
                sdel[q][tid] = (q==7) ? fmaxf(a,b) : (a+b);
            }
        }
        __syncthreads();
    }
    if (tid == 0){
        #pragma unroll
        for (int q=0;q<8;q++) g_part[blk*8+q] = sdel[q][0];
    }
}

// group means via prefix/select (no dynamic indexing): gt[i] = sum of v over group containing i
__device__ __forceinline__ void group_totals(const float v[8], const int same[7], float gt[8]){
    float gs[8];
    gs[0] = v[0];
    #pragma unroll
    for (int i=1;i<8;i++) gs[i] = v[i] + (same[i-1] ? gs[i-1] : 0.f);
    gt[7] = gs[7];
    #pragma unroll
    for (int i=6;i>=0;i--) gt[i] = same[i] ? gt[i+1] : gs[i];
}

// ---------------- kernels ----------------
__global__ void k_init(){
    g_minenc = 0xFFFFFFFFu;
    g_maxenc = 0u;
}

__global__ void k_minmax(const float* __restrict__ U){
    int tid = threadIdx.x;
    float lo =  INFINITY, hi = -INFINITY;
    size_t total = (size_t)NROWS * DTOT;
    for (size_t i = (size_t)blockIdx.x*blockDim.x + tid; i < total; i += (size_t)gridDim.x*blockDim.x){
        float u = U[i];
        lo = fminf(lo, u); hi = fmaxf(hi, u);
    }
    __shared__ float slo[256], shi[256];
    slo[tid]=lo; shi[tid]=hi;
    __syncthreads();
    for (int s=128; s; s>>=1){
        if (tid < s){ slo[tid]=fminf(slo[tid],slo[tid+s]); shi[tid]=fmaxf(shi[tid],shi[tid+s]); }
        __syncthreads();
    }
    if (tid == 0){
        atomicMin(&g_minenc, fenc(slo[0]));
        atomicMax(&g_maxenc, fenc(shi[0]));
    }
}

// level-0 residuals, per-column sort, delta stats (iteration 1 setup)
__global__ void k_sort1(const float* __restrict__ U){
    unsigned c = blockIdx.x*blockDim.x + threadIdx.x;
    int tid = threadIdx.x;
    float alpha = fdec(g_minenc), beta = fdec(g_maxenc);
    float s0 = (beta - alpha) / 3.0f;
    float v[8]; int id[8];
    #pragma unroll
    for (int r=0;r<8;r++){
        float u = U[(size_t)r*DTOT + c];
        v[r] = u - s0*floorf(u/s0);
        id[r] = r;
    }
    sort8(v, id);
    unsigned ord = 0;
    #pragma unroll
    for (int i=0;i<8;i++){
        g_sortedA[(size_t)i*DTOT + c] = v[i];
        ord |= (unsigned)id[i] << (3*i);
    }
    g_ordA[c] = ord;
    __shared__ float sdel[8][257];
    delta_stats(v, sdel, tid, blockIdx.x);
}

// reduce partials, compute global grouping scalars (sp, b, gid, counts, grad_g)
__global__ void k_scalar(const float* __restrict__ thres){
    __shared__ float sr[8][257];
    int tid = threadIdx.x;
    for (int q=0;q<8;q++){
        float a = 0.f;
        for (int p=tid; p<NBLK; p+=256){
            float x = g_part[p*8+q];
            a = (q==7) ? fmaxf(a,x) : (a+x);
        }
        sr[q][tid] = a;
    }
    __syncthreads();
    for (int s=128; s; s>>=1){
        if (tid < s){
            for (int q=0;q<8;q++){
                float a=sr[q][tid], b=sr[q][tid+s];
                sr[q][tid] = (q==7) ? fmaxf(a,b) : (a+b);
            }
        }
        __syncthreads();
    }
    if (tid == 0){
        float dmax = sr[7][0];
        float sigt = 1.0f/(1.0f + expf(-thres[0]));
        float sp[7], bv[7];
        int gid[8]; gid[0]=0;
        for (int i=0;i<7;i++){
            float mean = (sr[i][0]/dmax) * (1.0f/1048576.0f);
            float z = (mean - sigt)/0.01f;
            sp[i] = 1.0f/(1.0f + expf(-z));
            bv[i] = rintf(sp[i]);                      // round-half-even like jnp.round
            gid[i+1] = gid[i] + (int)bv[i];
        }
        int counts[8]; float glog[8];
        for (int g=0;g<8;g++){ counts[g]=0; glog[g]=0.f; }
        for (int r=0;r<8;r++) counts[gid[r]]++;
        for (int i=0;i<7;i++) glog[gid[i]] += logf(bv[i]==1.0f ? sp[i] : 1.0f - sp[i]);
        float gg[8];
        for (int g=0;g<8;g++) gg[g] = expf(glog[g]);
        for (int r=0;r<8;r++){ g_coef[r] = gg[gid[r]]; g_cnt[r] = (float)counts[gid[r]]; }
        for (int i=0;i<7;i++) g_same[i] = (bv[i]==0.0f) ? 1 : 0;
    }
}

// apply iteration-1 group update, recompute residuals, re-sort (iteration 2 setup)
__global__ void k_iter1(const float* __restrict__ U){
    unsigned c = blockIdx.x*blockDim.x + threadIdx.x;
    int tid = threadIdx.x;
    float alpha = fdec(g_minenc), beta = fdec(g_maxenc);
    float s0 = (beta - alpha)/3.0f;
    float s1 = s0/5.0f;
    float coef[8], cnt[8]; int same[7];
    #pragma unroll
    for (int i=0;i<8;i++){ coef[i]=g_coef[i]; cnt[i]=g_cnt[i]; }
    #pragma unroll
    for (int i=0;i<7;i++) same[i]=g_same[i];

    float v[8];
    #pragma unroll
    for (int i=0;i<8;i++) v[i] = g_sortedA[(size_t)i*DTOT + c];
    unsigned ord = g_ordA[c];

    float gt[8];
    group_totals(v, same, gt);

    float nv[8]; int nid[8];
    #pragma unroll
    for (int i=0;i<8;i++){
        float mean = gt[i]/cnt[i];
        float t    = coef[i]*mean;
        float add  = s1*floorf(t/s1);
        int orig   = (ord >> (3*i)) & 7;
        float u    = U[(size_t)orig*DTOT + c];
        float v0   = s0*floorf(u/s0);     // bitwise identical to k_sort1's level-0
        float vals1 = v0 + add;           // reference: vals_sum = vals_sum + s*floor(...)
        nv[i] = u - vals1;                // fresh residual, same op order as reference
        nid[i] = orig;
    }
    sort8(nv, nid);
    unsigned ord2 = 0;
    #pragma unroll
    for (int i=0;i<8;i++){
        g_sortedB[(size_t)i*DTOT + c] = nv[i];
        ord2 |= (unsigned)nid[i] << (3*i);
    }
    g_ordB[c] = ord2;
    __shared__ float sdel[8][257];
    delta_stats(nv, sdel, tid, blockIdx.x);
}

// apply iteration-2 group update, produce final quantized weights w
__global__ void k_final(const float* __restrict__ U){
    unsigned c = blockIdx.x*blockDim.x + threadIdx.x;
    float alpha = fdec(g_minenc), beta = fdec(g_maxenc);
    float s0 = (beta - alpha)/3.0f;
    float s1 = s0/5.0f;
    float s2 = s1/17.0f;
    float coef[8], cnt[8]; int same[7];
    #pragma unroll
    for (int i=0;i<8;i++){ coef[i]=g_coef[i]; cnt[i]=g_cnt[i]; }
    #pragma unroll
    for (int i=0;i<7;i++) same[i]=g_same[i];

    float v[8];
    #pragma unroll
    for (int i=0;i<8;i++) v[i] = g_sortedB[(size_t)i*DTOT + c];
    unsigned ord = g_ordB[c];

    float gt[8];
    group_totals(v, same, gt);

    #pragma unroll
    for (int i=0;i<8;i++){
        float mean = gt[i]/cnt[i];
        float t    = coef[i]*mean;
        float f2   = floorf(t/s2);
        int orig   = (ord >> (3*i)) & 7;
        float u    = U[(size_t)orig*DTOT + c];
        float vals1 = u - v[i];           // recover vals_sum (Sterbenz-exact in practice)
        g_w[(size_t)orig*DTOT + c] = vals1 + s2*f2;
    }
}

// ------------- batched fp32 GEMM: out[b,n,l] = sum_d x[b,n,d] * w[n,d,l] -------------
// 128x128 block tile, BK=16, 256 threads, 8x8 per-thread register tile.
__global__ __launch_bounds__(256) void k_gemm(const float* __restrict__ x, float* __restrict__ out){
    __shared__ float As[16][132];   // [k][m]
    __shared__ float Bs[16][132];   // [k][n]
    int n  = blockIdx.z;
    int bm = blockIdx.y * 128;      // b (batch) tile
    int bn = blockIdx.x * 128;      // l tile
    const float* Xn = x + n*D1;                      // x[b*8192 + n*1024 + d]
    const float* Wn = g_w + (size_t)n*DTOT;          // w[d*1024 + l]
    int tid = threadIdx.x;
    int tm = tid >> 4, tn = tid & 15;

    float acc[8][8];
    #pragma unroll
    for (int i=0;i<8;i++)
        #pragma unroll
        for (int j=0;j<8;j++) acc[i][j]=0.f;

    for (int k0=0; k0<D1; k0+=16){
        #pragma unroll
        for (int l=0;l<2;l++){
            int idx = tid + l*256;
            int row = idx >> 2;
            int c4  = idx & 3;
            float4 a = *reinterpret_cast<const float4*>(&Xn[(size_t)(bm+row)*8192 + k0 + c4*4]);
            As[c4*4+0][row]=a.x; As[c4*4+1][row]=a.y; As[c4*4+2][row]=a.z; As[c4*4+3][row]=a.w;
        }
        #pragma unroll
        for (int l=0;l<2;l++){
            int idx = tid + l*256;
            int kr = idx >> 5;
            int cc = idx & 31;
            float4 b = *reinterpret_cast<const float4*>(&Wn[(size_t)(k0+kr)*1024 + bn + cc*4]);
            *reinterpret_cast<float4*>(&Bs[kr][cc*4]) = b;
        }
        __syncthreads();
        #pragma unroll
        for (int k=0;k<16;k++){
            float ar[8], br[8];
            #pragma unroll
            for (int i=0;i<8;i++) ar[i]=As[k][tm*8+i];
            #pragma unroll
            for (int j=0;j<8;j++) br[j]=Bs[k][tn*8+j];
            #pragma unroll
            for (int i=0;i<8;i++)
                #pragma unroll
                for (int j=0;j<8;j++)
                    acc[i][j] += ar[i]*br[j];
        }
        __syncthreads();
    }
    #pragma unroll
    for (int i=0;i<8;i++){
        int row = bm + tm*8 + i;
        float* o = out + (size_t)row*8192 + n*1024 + bn + tn*8;
        float4 v0 = make_float4(acc[i][0],acc[i][1],acc[i][2],acc[i][3]);
        float4 v1 = make_float4(acc[i][4],acc[i][5],acc[i][6],acc[i][7]);
        reinterpret_cast<float4*>(o)[0] = v0;
        reinterpret_cast<float4*>(o)[1] = v1;
    }
}

// ---------------- launch ----------------
extern "C" void kernel_launch(void* const* d_in, const int* in_sizes, int n_in,
                              void* d_out, int out_size) {
    const float* x     = (const float*)d_in[0];   // [1024, 8, 1024]
    const float* U     = (const float*)d_in[1];   // [8, 1048576]
    const float* thres = (const float*)d_in[2];   // [1]
    float* out = (float*)d_out;                   // [1024, 8, 1024]

    k_init<<<1,1>>>();
    k_minmax<<<512,256>>>(U);
    k_sort1<<<NBLK,256>>>(U);
    k_scalar<<<1,256>>>(thres);
    k_iter1<<<NBLK,256>>>(U);
    k_scalar<<<1,256>>>(thres);
    k_final<<<NBLK,256>>>(U);
    k_gemm<<<dim3(D2/128, BB/128, NROWS),256>>>(x, out);
}

// round 2
// speedup vs baseline: 1.9649x; 1.9649x over previous
#include <cuda_runtime.h>
#include <cuda_fp16.h>
#include <math.h>
#include <stdint.h>

#define NROWS 8
#define DTOT  (1u<<20)      // 1048576 columns of U
#define D1    1024
#define D2    1024
#define BB    1024
#define NBLK  4096          // DTOT / 256

// ---------------- static device scratch (allocation-free rule) ----------------
__device__ float    g_sortedA[NROWS*DTOT];   // 32 MB
__device__ float    g_sortedB[NROWS*DTOT];   // 32 MB
__device__ unsigned g_ordA[DTOT];            // 4 MB (8 x 3-bit packed row ids)
__device__ unsigned g_ordB[DTOT];            // 4 MB
__device__ short    g_f01[NROWS*DTOT];       // 16 MB: 85*f0 + 17*f1 per element
__device__ __half   g_wh[NROWS*DTOT];        // 16 MB: Q = 85*f0+17*f1+f2 as fp16 (exact int)
__device__ __half   g_xh[NROWS*DTOT];        // 16 MB: x hi half, [n][b][d]
__device__ __half   g_xl[NROWS*DTOT];        // 16 MB: x lo half, [n][b][d]
__device__ float    g_part[NBLK*8];          // per-block partials: 7 delta sums + 1 delta max
__device__ unsigned g_minenc, g_maxenc;      // encoded min/max of U
__device__ float    g_coef[8];               // grad_g[gid[i]] per sorted row
__device__ float    g_cnt[8];                // counts[gid[i]] per sorted row (float)
__device__ int      g_same[7];               // 1 if sorted rows i,i+1 in same group (b==0)

// ---------------- helpers ----------------
__device__ __forceinline__ unsigned fenc(float f){
    unsigned u = __float_as_uint(f);
    return (u & 0x80000000u) ? ~u : (u | 0x80000000u);   // monotone float->uint
}
__device__ __forceinline__ float fdec(unsigned u){
    unsigned v = (u & 0x80000000u) ? (u & 0x7fffffffu) : ~u;
    return __uint_as_float(v);
}

// stable compare-exchange on (value, original-row) keys
__device__ __forceinline__ void ce(float &va, int &ia, float &vb, int &ib){
    bool sw = (va > vb) || (va == vb && ia > ib);
    if (sw){ float tv=va; va=vb; vb=tv; int ti=ia; ia=ib; ib=ti; }
}
// Batcher odd-even mergesort network for 8 elements (19 CEs), all static indices
__device__ __forceinline__ void sort8(float v[8], int id[8]){
    ce(v[0],id[0],v[1],id[1]); ce(v[2],id[2],v[3],id[3]); ce(v[4],id[4],v[5],id[5]); ce(v[6],id[6],v[7],id[7]);
    ce(v[0],id[0],v[2],id[2]); ce(v[1],id[1],v[3],id[3]); ce(v[4],id[4],v[6],id[6]); ce(v[5],id[5],v[7],id[7]);
    ce(v[1],id[1],v[2],id[2]); ce(v[5],id[5],v[6],id[6]);
    ce(v[0],id[0],v[4],id[4]); ce(v[1],id[1],v[5],id[5]); ce(v[2],id[2],v[6],id[6]); ce(v[3],id[3],v[7],id[7]);
    ce(v[2],id[2],v[4],id[4]); ce(v[3],id[3],v[5],id[5]);
    ce(v[1],id[1],v[2],id[2]); ce(v[3],id[3],v[4],id[4]); ce(v[5],id[5],v[6],id[6]);
}

// block-reduce 7 delta sums + delta max into g_part[blk*8 + q]
__device__ __forceinline__ void delta_stats(const float v[8], float (*sdel)[257], int tid, int blk){
    #pragma unroll
    for (int i=0;i<7;i++) sdel[i][tid] = v[i+1]-v[i];
    float mx = 0.f;
    #pragma unroll
    for (int i=0;i<7;i++) mx = fmaxf(mx, v[i+1]-v[i]);
    sdel[7][tid] = mx;
    __syncthreads();
    for (int s=128; s; s>>=1){
        if (tid < s){
            #pragma unroll
            for (int q=0;q<8;q++){
                float a = sdel[q][tid], b = sdel[q][tid+s];
                sdel[q][tid] = (q==7) ? fmaxf(a,b) : (a+b);
            }
        }
        __syncthreads();
    }
    if (tid == 0){
        #pragma unroll
        for (int q=0;q<8;q++) g_part[blk*8+q] = sdel[q][0];
    }
}

// group totals via prefix/select: gt[i] = sum of v over group containing sorted row i
__device__ __forceinline__ void group_totals(const float v[8], const int same[7], float gt[8]){
    float gs[8];
    gs[0] = v[0];
    #pragma unroll
    for (int i=1;i<8;i++) gs[i] = v[i] + (same[i-1] ? gs[i-1] : 0.f);
    gt[7] = gs[7];
    #pragma unroll
    for (int i=6;i>=0;i--) gt[i] = same[i] ? gt[i+1] : gs[i];
}

// ---------------- quant kernels ----------------
__global__ void k_init(){
    g_minenc = 0xFFFFFFFFu;
    g_maxenc = 0u;
}

__global__ void k_minmax(const float* __restrict__ U){
    int tid = threadIdx.x;
    float lo =  INFINITY, hi = -INFINITY;
    size_t total = (size_t)NROWS * DTOT;
    for (size_t i = (size_t)blockIdx.x*blockDim.x + tid; i < total; i += (size_t)gridDim.x*blockDim.x){
        float u = U[i];
        lo = fminf(lo, u); hi = fmaxf(hi, u);
    }
    __shared__ float slo[256], shi[256];
    slo[tid]=lo; shi[tid]=hi;
    __syncthreads();
    for (int s=128; s; s>>=1){
        if (tid < s){ slo[tid]=fminf(slo[tid],slo[tid+s]); shi[tid]=fmaxf(shi[tid],shi[tid+s]); }
        __syncthreads();
    }
    if (tid == 0){
        atomicMin(&g_minenc, fenc(slo[0]));
        atomicMax(&g_maxenc, fenc(shi[0]));
    }
}

// level-0 residuals, per-column sort, delta stats (iteration 1 setup)
__global__ void k_sort1(const float* __restrict__ U){
    unsigned c = blockIdx.x*blockDim.x + threadIdx.x;
    int tid = threadIdx.x;
    float alpha = fdec(g_minenc), beta = fdec(g_maxenc);
    float s0 = (beta - alpha) / 3.0f;
    float v[8]; int id[8];
    #pragma unroll
    for (int r=0;r<8;r++){
        float u = U[(size_t)r*DTOT + c];
        v[r] = u - s0*floorf(u/s0);
        id[r] = r;
    }
    sort8(v, id);
    unsigned ord = 0;
    #pragma unroll
    for (int i=0;i<8;i++){
        g_sortedA[(size_t)i*DTOT + c] = v[i];
        ord |= (unsigned)id[i] << (3*i);
    }
    g_ordA[c] = ord;
    __shared__ float sdel[8][257];
    delta_stats(v, sdel, tid, blockIdx.x);
}

// reduce partials, compute global grouping scalars (sp, b, gid, counts, grad_g)
__global__ void k_scalar(const float* __restrict__ thres){
    __shared__ float sr[8][1025];
    int tid = threadIdx.x;
    for (int q=0;q<8;q++){
        float a = 0.f;
        for (int p=tid; p<NBLK; p+=1024){
            float x = g_part[p*8+q];
            a = (q==7) ? fmaxf(a,x) : (a+x);
        }
        sr[q][tid] = a;
    }
    __syncthreads();
    for (int s=512; s; s>>=1){
        if (tid < s){
            for (int q=0;q<8;q++){
                float a=sr[q][tid], b=sr[q][tid+s];
                sr[q][tid] = (q==7) ? fmaxf(a,b) : (a+b);
            }
        }
        __syncthreads();
    }
    if (tid == 0){
        float dmax = sr[7][0];
        float sigt = 1.0f/(1.0f + expf(-thres[0]));
        float sp[7], bv[7];
        int gid[8]; gid[0]=0;
        for (int i=0;i<7;i++){
            float mean = (sr[i][0]/dmax) * (1.0f/1048576.0f);
            float z = (mean - sigt)/0.01f;
            sp[i] = 1.0f/(1.0f + expf(-z));
            bv[i] = rintf(sp[i]);                      // round-half-even like jnp.round
            gid[i+1] = gid[i] + (int)bv[i];
        }
        int counts[8]; float glog[8];
        for (int g=0;g<8;g++){ counts[g]=0; glog[g]=0.f; }
        for (int r=0;r<8;r++) counts[gid[r]]++;
        for (int i=0;i<7;i++) glog[gid[i]] += logf(bv[i]==1.0f ? sp[i] : 1.0f - sp[i]);
        float gg[8];
        for (int g=0;g<8;g++) gg[g] = expf(glog[g]);
        for (int r=0;r<8;r++){ g_coef[r] = gg[gid[r]]; g_cnt[r] = (float)counts[gid[r]]; }
        for (int i=0;i<7;i++) g_same[i] = (bv[i]==0.0f) ? 1 : 0;
    }
}

// apply iteration-1 group update, record f01, recompute residuals, re-sort
__global__ void k_iter1(const float* __restrict__ U){
    unsigned c = blockIdx.x*blockDim.x + threadIdx.x;
    int tid = threadIdx.x;
    float alpha = fdec(g_minenc), beta = fdec(g_maxenc);
    float s0 = (beta - alpha)/3.0f;
    float s1 = s0/5.0f;
    float coef[8], cnt[8]; int same[7];
    #pragma unroll
    for (int i=0;i<8;i++){ coef[i]=g_coef[i]; cnt[i]=g_cnt[i]; }
    #pragma unroll
    for (int i=0;i<7;i++) same[i]=g_same[i];

    float v[8];
    #pragma unroll
    for (int i=0;i<8;i++) v[i] = g_sortedA[(size_t)i*DTOT + c];
    unsigned ord = g_ordA[c];

    float gt[8];
    group_totals(v, same, gt);

    float nv[8]; int nid[8];
    #pragma unroll
    for (int i=0;i<8;i++){
        float mean = gt[i]/cnt[i];
        float t    = coef[i]*mean;
        float f1f  = floorf(t/s1);
        float add  = s1*f1f;
        int orig   = (ord >> (3*i)) & 7;
        float u    = U[(size_t)orig*DTOT + c];
        float f0f  = floorf(u/s0);        // bitwise identical to k_sort1's level-0 floor
        float v0   = s0*f0f;
        float vals1 = v0 + add;           // reference op order
        nv[i] = u - vals1;                // fresh residual
        nid[i] = orig;
        g_f01[(size_t)orig*DTOT + c] = (short)(85*(int)f0f + 17*(int)f1f);
    }
    sort8(nv, nid);
    unsigned ord2 = 0;
    #pragma unroll
    for (int i=0;i<8;i++){
        g_sortedB[(size_t)i*DTOT + c] = nv[i];
        ord2 |= (unsigned)nid[i] << (3*i);
    }
    g_ordB[c] = ord2;
    __shared__ float sdel[8][257];
    delta_stats(nv, sdel, tid, blockIdx.x);
}

// apply iteration-2 group update, produce final integer weights Q in fp16
__global__ void k_final(){
    unsigned c = blockIdx.x*blockDim.x + threadIdx.x;
    float alpha = fdec(g_minenc), beta = fdec(g_maxenc);
    float s0 = (beta - alpha)/3.0f;
    float s1 = s0/5.0f;
    float s2 = s1/17.0f;
    float coef[8], cnt[8]; int same[7];
    #pragma unroll
    for (int i=0;i<8;i++){ coef[i]=g_coef[i]; cnt[i]=g_cnt[i]; }
    #pragma unroll
    for (int i=0;i<7;i++) same[i]=g_same[i];

    float v[8];
    #pragma unroll
    for (int i=0;i<8;i++) v[i] = g_sortedB[(size_t)i*DTOT + c];
    unsigned ord = g_ordB[c];

    float gt[8];
    group_totals(v, same, gt);

    #pragma unroll
    for (int i=0;i<8;i++){
        float mean = gt[i]/cnt[i];
        float t    = coef[i]*mean;
        int if2    = (int)floorf(t/s2);
        int orig   = (ord >> (3*i)) & 7;
        int Q      = (int)g_f01[(size_t)orig*DTOT + c] + if2;
        g_wh[(size_t)orig*DTOT + c] = __float2half_rn((float)Q);  // exact: |Q| << 2048
    }
}

// split x (fp32, [b][n][d]) into hi/lo fp16 pair, repacked as [n][b][d]
__global__ void k_split(const float* __restrict__ x){
    unsigned i = blockIdx.x*blockDim.x + threadIdx.x;   // 8M elements
    unsigned d = i & 1023u;
    unsigned n = (i >> 10) & 7u;
    unsigned b = i >> 13;
    float xv = x[i];
    __half hh = __float2half_rn(xv);
    __half hl = __float2half_rn(xv - __half2float(hh));
    unsigned j = (n << 20) | (b << 10) | d;
    g_xh[j] = hh;
    g_xl[j] = hl;
}

// ---------------- fp16 tensor-core GEMM ----------------
// out[b,n,l] = s2 * sum_d (xh+xl)[n,b,d] * Q[n,d,l]
// block tile 128(M=b) x 128(N=l) x 32(K=d), 8 warps (4x2), warp tile 32x64,
// mma.sync m16n8k16 f16->f32, cp.async double buffer, ldmatrix fragments.
#define SA_STRIDE 40          // halfs per A smem row (pad 32->40)
#define SB_STRIDE 136         // halfs per B smem row (pad 128->136)
#define SA_STAGE  (128*SA_STRIDE)
#define SB_STAGE  (32*SB_STRIDE)
#define SMEM_HALFS (4*SA_STAGE + 2*SB_STAGE)   // Ah(2) + Al(2) + B(2)
#define SMEM_BYTES (SMEM_HALFS*2)

__device__ __forceinline__ void ldsm_x4(uint32_t r[4], uint32_t addr){
    asm volatile("ldmatrix.sync.aligned.m8n8.x4.shared.b16 {%0,%1,%2,%3}, [%4];"
        : "=r"(r[0]),"=r"(r[1]),"=r"(r[2]),"=r"(r[3]) : "r"(addr));
}
__device__ __forceinline__ void ldsm_x2t(uint32_t r[2], uint32_t addr){
    asm volatile("ldmatrix.sync.aligned.m8n8.x2.trans.shared.b16 {%0,%1}, [%2];"
        : "=r"(r[0]),"=r"(r[1]) : "r"(addr));
}
__device__ __forceinline__ void mma16816(float c[4], const uint32_t a[4], const uint32_t b[2]){
    asm volatile("mma.sync.aligned.m16n8k16.row.col.f32.f16.f16.f32 "
        "{%0,%1,%2,%3}, {%4,%5,%6,%7}, {%8,%9}, {%0,%1,%2,%3};"
        : "+f"(c[0]),"+f"(c[1]),"+f"(c[2]),"+f"(c[3])
        : "r"(a[0]),"r"(a[1]),"r"(a[2]),"r"(a[3]), "r"(b[0]),"r"(b[1]));
}
__device__ __forceinline__ void cpasync16(uint32_t dst, const void* src){
    asm volatile("cp.async.cg.shared.global [%0], [%1], 16;" :: "r"(dst), "l"(src));
}

__device__ __forceinline__ void gemm_load_stage(
    const __half* Ah, const __half* Al, const __half* Bn,
    uint32_t sAh_u, uint32_t sAl_u, uint32_t sB_u,
    int bm, int bn, int k0, int st, int tid)
{
    #pragma unroll
    for (int i=0;i<2;i++){
        int ch = tid + i*256;
        int r  = ch >> 2, sg = ch & 3;
        const __half* srch = Ah + (size_t)(bm+r)*1024 + k0 + sg*8;
        const __half* srcl = Al + (size_t)(bm+r)*1024 + k0 + sg*8;
        uint32_t off = (uint32_t)(st*SA_STAGE + r*SA_STRIDE + sg*8)*2u;
        cpasync16(sAh_u + off, srch);
        cpasync16(sAl_u + off, srcl);
        int kr = ch >> 4, ns = ch & 15;
        const __half* srcb = Bn + (size_t)(k0+kr)*1024 + bn + ns*8;
        uint32_t offb = (uint32_t)(st*SB_STAGE + kr*SB_STRIDE + ns*8)*2u;
        cpasync16(sB_u + offb, srcb);
    }
    asm volatile("cp.async.commit_group;");
}

__global__ __launch_bounds__(256) void k_gemm_h(float* __restrict__ out){
    extern __shared__ __half smem[];
    __half* sAh = smem;
    __half* sAl = smem + 2*SA_STAGE;
    __half* sB  = smem + 4*SA_STAGE;

    int n  = blockIdx.z;
    int bm = blockIdx.y * 128;
    int bn = blockIdx.x * 128;
    const __half* An_h = g_xh + ((size_t)n << 20);
    const __half* An_l = g_xl + ((size_t)n << 20);
    const __half* Bn   = g_wh + ((size_t)n << 20);

    int tid  = threadIdx.x;
    int lane = tid & 31;
    int warp = tid >> 5;
    int wm = (warp >> 1) * 32;
    int wn = (warp & 1) * 64;

    uint32_t sAh_u = (uint32_t)__cvta_generic_to_shared(sAh);
    uint32_t sAl_u = (uint32_t)__cvta_generic_to_shared(sAl);
    uint32_t sB_u  = (uint32_t)__cvta_generic_to_shared(sB);

    float c[2][8][4];
    #pragma unroll
    for (int mt=0;mt<2;mt++)
        #pragma unroll
        for (int nt=0;nt<8;nt++)
            #pragma unroll
            for (int q=0;q<4;q++) c[mt][nt][q] = 0.f;

    gemm_load_stage(An_h, An_l, Bn, sAh_u, sAl_u, sB_u, bm, bn, 0, 0, tid);

    for (int it=0; it<32; it++){
        int st = it & 1;
        if (it+1 < 32){
            gemm_load_stage(An_h, An_l, Bn, sAh_u, sAl_u, sB_u, bm, bn, (it+1)*32, st^1, tid);
            asm volatile("cp.async.wait_group 1;");
        } else {
            asm volatile("cp.async.wait_group 0;");
        }
        __syncthreads();

        #pragma unroll
        for (int kk=0; kk<32; kk+=16){
            uint32_t ah[2][4], al[2][4], bf[8][2];
            #pragma unroll
            for (int mt=0; mt<2; mt++){
                int row = wm + mt*16 + (lane & 15);
                int col = kk + ((lane >> 4) << 3);
                uint32_t off = (uint32_t)(st*SA_STAGE + row*SA_STRIDE + col)*2u;
                ldsm_x4(ah[mt], sAh_u + off);
                ldsm_x4(al[mt], sAl_u + off);
            }
            #pragma unroll
            for (int nt=0; nt<8; nt++){
                int krow = kk + (lane & 15);
                uint32_t off = (uint32_t)(st*SB_STAGE + krow*SB_STRIDE + wn + nt*8)*2u;
                ldsm_x2t(bf[nt], sB_u + off);
            }
            #pragma unroll
            for (int mt=0;mt<2;mt++)
                #pragma unroll
                for (int nt=0;nt<8;nt++){
                    mma16816(c[mt][nt], ah[mt], bf[nt]);
                    mma16816(c[mt][nt], al[mt], bf[nt]);
                }
        }
        __syncthreads();
    }

    // epilogue: scale by s2 and store
    float alpha = fdec(g_minenc), beta = fdec(g_maxenc);
    float s2 = ((beta - alpha)/3.0f/5.0f)/17.0f;
    #pragma unroll
    for (int mt=0;mt<2;mt++){
        int r0 = bm + wm + mt*16 + (lane >> 2);
        #pragma unroll
        for (int nt=0;nt<8;nt++){
            int cb = bn + wn + nt*8 + (lane & 3)*2;
            float2 v0 = make_float2(c[mt][nt][0]*s2, c[mt][nt][1]*s2);
            float2 v1 = make_float2(c[mt][nt][2]*s2, c[mt][nt][3]*s2);
            *reinterpret_cast<float2*>(out + (size_t)r0*8192 + n*1024 + cb)       = v0;
            *reinterpret_cast<float2*>(out + (size_t)(r0+8)*8192 + n*1024 + cb)   = v1;
        }
    }
}

// ---------------- launch ----------------
extern "C" void kernel_launch(void* const* d_in, const int* in_sizes, int n_in,
                              void* d_out, int out_size) {
    const float* x     = (const float*)d_in[0];   // [1024, 8, 1024]
    const float* U     = (const float*)d_in[1];   // [8, 1048576]
    const float* thres = (const float*)d_in[2];   // [1]
    float* out = (float*)d_out;                   // [1024, 8, 1024]

    cudaFuncSetAttribute(k_gemm_h, cudaFuncAttributeMaxDynamicSharedMemorySize, SMEM_BYTES);

    k_init<<<1,1>>>();
    k_minmax<<<512,256>>>(U);
    k_split<<<8192,1024>>>(x);          // independent of quant chain
    k_sort1<<<NBLK,256>>>(U);
    k_scalar<<<1,1024>>>(thres);
    k_iter1<<<NBLK,256>>>(U);
    k_scalar<<<1,1024>>>(thres);
    k_final<<<NBLK,256>>>();
    k_gemm_h<<<dim3(D2/128, BB/128, NROWS), 256, SMEM_BYTES>>>(out);
}

// round 4
// speedup vs baseline: 2.5327x; 1.2890x over previous
#include <cuda_runtime.h>
#include <cuda_fp16.h>
#include <math.h>
#include <stdint.h>

#define NROWS 8
#define DTOT  (1u<<20)      // 1048576 columns of U
#define PBLK  2048          // pass-kernel blocks (256 thr x 2 cols)

// ---------------- static device scratch (allocation-free rule) ----------------
__device__ __half   g_wh[NROWS*DTOT];        // 16 MB: Q [n][d][l] (exact small int in fp16)
__device__ __half   g_xh[NROWS*DTOT];        // 16 MB: x hi half, [n][b][d]
__device__ float    g_part[8*PBLK];          // partials laid out [q][blk]
__device__ unsigned g_minenc, g_maxenc;      // encoded min/max of U
__device__ float    g_coefs[2][8];           // grad_g[gid[i]] per sorted row, per iteration
__device__ float    g_cnts[2][8];            // counts[gid[i]] per sorted row
__device__ int      g_sames[2][7];           // 1 if sorted rows i,i+1 in same group

// ---------------- helpers ----------------
__device__ __forceinline__ unsigned fenc(float f){
    unsigned u = __float_as_uint(f);
    return (u & 0x80000000u) ? ~u : (u | 0x80000000u);
}
__device__ __forceinline__ float fdec(unsigned u){
    unsigned v = (u & 0x80000000u) ? (u & 0x7fffffffu) : ~u;
    return __uint_as_float(v);
}

// values-only compare-exchange (stability irrelevant for pure values)
__device__ __forceinline__ void cev(float &a, float &b){
    float lo = fminf(a,b), hi = fmaxf(a,b);
    a = lo; b = hi;
}
__device__ __forceinline__ void sortv8(float v[8]){
    cev(v[0],v[1]); cev(v[2],v[3]); cev(v[4],v[5]); cev(v[6],v[7]);
    cev(v[0],v[2]); cev(v[1],v[3]); cev(v[4],v[6]); cev(v[5],v[7]);
    cev(v[1],v[2]); cev(v[5],v[6]);
    cev(v[0],v[4]); cev(v[1],v[5]); cev(v[2],v[6]); cev(v[3],v[7]);
    cev(v[2],v[4]); cev(v[3],v[5]);
    cev(v[1],v[2]); cev(v[3],v[4]); cev(v[5],v[6]);
}
// stable (value,id) sort carrying one float payload
__device__ __forceinline__ void ce3(float &va, int &ia, float &pa, float &vb, int &ib, float &pb){
    bool sw = (va > vb) || (va == vb && ia > ib);
    if (sw){ float tv=va; va=vb; vb=tv; int ti=ia; ia=ib; ib=ti; float tp=pa; pa=pb; pb=tp; }
}
__device__ __forceinline__ void sort8p(float v[8], int id[8], float p[8]){
    ce3(v[0],id[0],p[0],v[1],id[1],p[1]); ce3(v[2],id[2],p[2],v[3],id[3],p[3]); ce3(v[4],id[4],p[4],v[5],id[5],p[5]); ce3(v[6],id[6],p[6],v[7],id[7],p[7]);
    ce3(v[0],id[0],p[0],v[2],id[2],p[2]); ce3(v[1],id[1],p[1],v[3],id[3],p[3]); ce3(v[4],id[4],p[4],v[6],id[6],p[6]); ce3(v[5],id[5],p[5],v[7],id[7],p[7]);
    ce3(v[1],id[1],p[1],v[2],id[2],p[2]); ce3(v[5],id[5],p[5],v[6],id[6],p[6]);
    ce3(v[0],id[0],p[0],v[4],id[4],p[4]); ce3(v[1],id[1],p[1],v[5],id[5],p[5]); ce3(v[2],id[2],p[2],v[6],id[6],p[6]); ce3(v[3],id[3],p[3],v[7],id[7],p[7]);
    ce3(v[2],id[2],p[2],v[4],id[4],p[4]); ce3(v[3],id[3],p[3],v[5],id[5],p[5]);
    ce3(v[1],id[1],p[1],v[2],id[2],p[2]); ce3(v[3],id[3],p[3],v[4],id[4],p[4]); ce3(v[5],id[5],p[5],v[6],id[6],p[6]);
}

// group totals via prefix/select using global same flags
__device__ __forceinline__ void group_totals_g(const float v[8], const int* sameg, float gt[8]){
    int same[7];
    #pragma unroll
    for (int i=0;i<7;i++) same[i] = sameg[i];
    float gs[8];
    gs[0] = v[0];
    #pragma unroll
    for (int i=1;i<8;i++) gs[i] = v[i] + (same[i-1] ? gs[i-1] : 0.f);
    gt[7] = gs[7];
    #pragma unroll
    for (int i=6;i>=0;i--) gt[i] = same[i] ? gt[i+1] : gs[i];
}

// two-column delta stats: warp shuffle + one tiny smem round
__device__ __forceinline__ void delta_stats2(const float va[8], const float vb[8], int tid, int blk){
    float d[8];
    float mx = 0.f;
    #pragma unroll
    for (int q=0;q<7;q++){
        float da = va[q+1]-va[q];
        float db = vb[q+1]-vb[q];
        d[q] = da + db;
        mx = fmaxf(mx, fmaxf(da, db));
    }
    d[7] = mx;
    #pragma unroll
    for (int off=16; off; off>>=1){
        #pragma unroll
        for (int q=0;q<7;q++) d[q] += __shfl_xor_sync(0xffffffffu, d[q], off);
        d[7] = fmaxf(d[7], __shfl_xor_sync(0xffffffffu, d[7], off));
    }
    __shared__ float sw[8][8];
    int w = tid>>5;
    if ((tid&31)==0){
        #pragma unroll
        for (int q=0;q<8;q++) sw[w][q]=d[q];
    }
    __syncthreads();
    if (tid < 8){
        int q = tid;
        float a = sw[0][q];
        if (q==7){
            #pragma unroll
            for (int w2=1;w2<8;w2++) a = fmaxf(a, sw[w2][q]);
        } else {
            #pragma unroll
            for (int w2=1;w2<8;w2++) a += sw[w2][q];
        }
        g_part[q*PBLK + blk] = a;
    }
}

// ---------------- quant kernels ----------------
__global__ void k_init(){
    g_minenc = 0xFFFFFFFFu;
    g_maxenc = 0u;
}

__global__ void k_minmax(const float* __restrict__ U){
    int tid = threadIdx.x;
    float lo =  INFINITY, hi = -INFINITY;
    size_t total = (size_t)NROWS * DTOT;
    for (size_t i = (size_t)blockIdx.x*blockDim.x + tid; i < total; i += (size_t)gridDim.x*blockDim.x){
        float u = U[i];
        lo = fminf(lo, u); hi = fmaxf(hi, u);
    }
    __shared__ float slo[256], shi[256];
    slo[tid]=lo; shi[tid]=hi;
    __syncthreads();
    for (int s=128; s; s>>=1){
        if (tid < s){ slo[tid]=fminf(slo[tid],slo[tid+s]); shi[tid]=fmaxf(shi[tid],shi[tid+s]); }
        __syncthreads();
    }
    if (tid == 0){
        atomicMin(&g_minenc, fenc(slo[0]));
        atomicMax(&g_maxenc, fenc(shi[0]));
    }
}

// pass 1: level-0 residuals, per-column value sort, delta stats; 2 cols/thread
__global__ void k_pass1(const float* __restrict__ U){
    unsigned c0 = blockIdx.x*512u + threadIdx.x;
    unsigned c1 = c0 + 256u;
    float alpha = fdec(g_minenc), beta = fdec(g_maxenc);
    float s0 = (beta - alpha) / 3.0f;
    float va[8], vb[8];
    #pragma unroll
    for (int r=0;r<8;r++){
        float ua = U[(size_t)r*DTOT + c0];
        float ub = U[(size_t)r*DTOT + c1];
        va[r] = ua - s0*floorf(ua/s0);
        vb[r] = ub - s0*floorf(ub/s0);
    }
    sortv8(va); sortv8(vb);
    delta_stats2(va, vb, threadIdx.x, blockIdx.x);
}

// reduce partials, compute global grouping scalars for iteration `set`
__global__ void k_scalar(const float* __restrict__ thres, int set){
    int tid = threadIdx.x;        // 1024
    int q = tid >> 7;
    int r = tid & 127;
    float a = 0.f;
    for (int p=r; p<PBLK; p+=128){
        float xv = g_part[q*PBLK + p];
        a = (q==7) ? fmaxf(a,xv) : (a+xv);
    }
    #pragma unroll
    for (int off=16; off; off>>=1){
        float b = __shfl_xor_sync(0xffffffffu, a, off);
        a = (q==7) ? fmaxf(a,b) : (a+b);
    }
    __shared__ float s4[8][4];
    __shared__ float sred[8];
    if ((tid&31)==0) s4[q][(tid>>5)&3] = a;
    __syncthreads();
    if (tid < 8){
        float x0=s4[tid][0], x1=s4[tid][1], x2=s4[tid][2], x3=s4[tid][3];
        sred[tid] = (tid==7) ? fmaxf(fmaxf(x0,x1),fmaxf(x2,x3)) : ((x0+x1)+(x2+x3));
    }
    __syncthreads();
    if (tid==0){
        float dmax = sred[7];
        float sigt = 1.0f/(1.0f + expf(-thres[0]));
        float sp[7], bv[7];
        int gid[8]; gid[0]=0;
        for (int i=0;i<7;i++){
            float mean = (sred[i]/dmax) * (1.0f/1048576.0f);
            float z = (mean - sigt)/0.01f;
            sp[i] = 1.0f/(1.0f + expf(-z));
            bv[i] = rintf(sp[i]);
            gid[i+1] = gid[i] + (int)bv[i];
        }
        int counts[8]; float glog[8];
        for (int g=0;g<8;g++){ counts[g]=0; glog[g]=0.f; }
        for (int rr=0;rr<8;rr++) counts[gid[rr]]++;
        for (int i=0;i<7;i++) glog[gid[i]] += logf(bv[i]==1.0f ? sp[i] : 1.0f - sp[i]);
        float gg[8];
        for (int g=0;g<8;g++) gg[g] = expf(glog[g]);
        for (int rr=0;rr<8;rr++){ g_coefs[set][rr] = gg[gid[rr]]; g_cnts[set][rr] = (float)counts[gid[rr]]; }
        for (int i=0;i<7;i++) g_sames[set][i] = (bv[i]==0.0f) ? 1 : 0;
    }
}

// one column of pass2 work: residual->sort->group update->new residual (sorted values)
__device__ __forceinline__ void pass2_col(const float* __restrict__ U, unsigned c,
                                          float s0, float s1, float nv[8]){
    float v[8], u[8]; int id[8];
    #pragma unroll
    for (int r=0;r<8;r++){
        float uu = U[(size_t)r*DTOT + c];
        u[r] = uu;
        v[r] = uu - s0*floorf(uu/s0);
        id[r] = r;
    }
    sort8p(v, id, u);
    float gt[8];
    group_totals_g(v, g_sames[0], gt);
    #pragma unroll
    for (int i=0;i<8;i++){
        float mean = gt[i]/g_cnts[0][i];
        float t    = g_coefs[0][i]*mean;
        float add  = s1*floorf(t/s1);
        float f0   = floorf(u[i]/s0);   // bitwise identical to the level-0 floor
        float v0   = s0*f0;
        float vals1 = v0 + add;         // reference op order
        nv[i] = u[i] - vals1;
    }
    sortv8(nv);
}

// pass 2: recompute, apply iter-1 update, re-sort residuals, delta stats; 2 cols/thread
__global__ void k_pass2(const float* __restrict__ U){
    unsigned c0 = blockIdx.x*512u + threadIdx.x;
    unsigned c1 = c0 + 256u;
    float alpha = fdec(g_minenc), beta = fdec(g_maxenc);
    float s0 = (beta - alpha)/3.0f;
    float s1 = s0/5.0f;
    float na[8], nb[8];
    pass2_col(U, c0, s0, s1, na);
    pass2_col(U, c1, s0, s1, nb);
    delta_stats2(na, nb, threadIdx.x, blockIdx.x);
}

// final: full recompute, iter-2 update, emit Q in fp16 (exact small int)
__global__ void k_final(const float* __restrict__ U){
    unsigned c = blockIdx.x*blockDim.x + threadIdx.x;
    float alpha = fdec(g_minenc), beta = fdec(g_maxenc);
    float s0 = (beta - alpha)/3.0f;
    float s1 = s0/5.0f;
    float s2 = s1/17.0f;

    float v[8], u[8]; int id[8];
    #pragma unroll
    for (int r=0;r<8;r++){
        float uu = U[(size_t)r*DTOT + c];
        u[r] = uu;
        v[r] = uu - s0*floorf(uu/s0);
        id[r] = r;
    }
    sort8p(v, id, u);

    float gt[8];
    group_totals_g(v, g_sames[0], gt);

    float nv[8], pay[8]; int nid[8];
    #pragma unroll
    for (int i=0;i<8;i++){
        float mean = gt[i]/g_cnts[0][i];
        float t    = g_coefs[0][i]*mean;
        float f1f  = floorf(t/s1);
        float add  = s1*f1f;
        float f0f  = floorf(u[i]/s0);
        float v0   = s0*f0f;
        float vals1 = v0 + add;
        nv[i]  = u[i] - vals1;
        nid[i] = id[i];
        pay[i] = 85.0f*f0f + 17.0f*f1f;   // exact small integer
    }
    sort8p(nv, nid, pay);

    float gt2[8];
    group_totals_g(nv, g_sames[1], gt2);

    #pragma unroll
    for (int j=0;j<8;j++){
        float mean = gt2[j]/g_cnts[1][j];
        float t    = g_coefs[1][j]*mean;
        float f2f  = floorf(t/s2);
        float Q    = pay[j] + f2f;        // |Q| < 512 -> exact in fp16
        g_wh[(size_t)nid[j]*DTOT + c] = __float2half_rn(Q);
    }
}

// split x (fp32, [b][n][d]) into hi fp16, repacked as [n][b][d]; 4 elems/thread
__global__ void k_split(const float* __restrict__ x){
    unsigned idx = blockIdx.x*1024u + threadIdx.x;   // 2M threads
    unsigned base = idx*4u;
    unsigned d = base & 1023u;
    unsigned n = (base >> 10) & 7u;
    unsigned b = base >> 13;
    float4 xv = *reinterpret_cast<const float4*>(x + base);
    __half2 h0 = __floats2half2_rn(xv.x, xv.y);
    __half2 h1 = __floats2half2_rn(xv.z, xv.w);
    unsigned j = (n << 20) | (b << 10) | d;
    *reinterpret_cast<__half2*>(g_xh + j)     = h0;
    *reinterpret_cast<__half2*>(g_xh + j + 2) = h1;
}

// ---------------- fp16 mma.sync GEMM (hi-only) ----------------
// out[b,n,l] = s2 * sum_d xh[n,b,d] * Q[n,d,l]
// block tile 128(M=b) x 128(N=l) x 32(K=d), 8 warps (4x2), warp tile 32x64,
// mma.sync m16n8k16 f16->f32, cp.async double buffer, ldmatrix fragments.
#define SA_STRIDE 40          // halfs per A smem row (pad 32->40)
#define SB_STRIDE 136         // halfs per B smem row (pad 128->136)
#define SA_STAGE  (128*SA_STRIDE)
#define SB_STAGE  (32*SB_STRIDE)
#define SMEM_HALFS (2*SA_STAGE + 2*SB_STAGE)
#define SMEM_BYTES (SMEM_HALFS*2)

__device__ __forceinline__ void ldsm_x4(uint32_t r[4], uint32_t addr){
    asm volatile("ldmatrix.sync.aligned.m8n8.x4.shared.b16 {%0,%1,%2,%3}, [%4];"
        : "=r"(r[0]),"=r"(r[1]),"=r"(r[2]),"=r"(r[3]) : "r"(addr));
}
__device__ __forceinline__ void ldsm_x2t(uint32_t r[2], uint32_t addr){
    asm volatile("ldmatrix.sync.aligned.m8n8.x2.trans.shared.b16 {%0,%1}, [%2];"
        : "=r"(r[0]),"=r"(r[1]) : "r"(addr));
}
__device__ __forceinline__ void mma16816(float c[4], const uint32_t a[4], const uint32_t b[2]){
    asm volatile("mma.sync.aligned.m16n8k16.row.col.f32.f16.f16.f32 "
        "{%0,%1,%2,%3}, {%4,%5,%6,%7}, {%8,%9}, {%0,%1,%2,%3};"
        : "+f"(c[0]),"+f"(c[1]),"+f"(c[2]),"+f"(c[3])
        : "r"(a[0]),"r"(a[1]),"r"(a[2]),"r"(a[3]), "r"(b[0]),"r"(b[1]));
}
__device__ __forceinline__ void cpasync16(uint32_t dst, const void* src){
    asm volatile("cp.async.cg.shared.global [%0], [%1], 16;" :: "r"(dst), "l"(src));
}

__device__ __forceinline__ void gemm_load_stage(
    const __half* Ah, const __half* Bn,
    uint32_t sA_u, uint32_t sB_u,
    int bm, int bn, int k0, int st, int tid)
{
    #pragma unroll
    for (int i=0;i<2;i++){
        int ch = tid + i*256;
        int r  = ch >> 2, sg = ch & 3;
        const __half* srch = Ah + (size_t)(bm+r)*1024 + k0 + sg*8;
        uint32_t off = (uint32_t)(st*SA_STAGE + r*SA_STRIDE + sg*8)*2u;
        cpasync16(sA_u + off, srch);
        int kr = ch >> 4, ns = ch & 15;
        const __half* srcb = Bn + (size_t)(k0+kr)*1024 + bn + ns*8;
        uint32_t offb = (uint32_t)(st*SB_STAGE + kr*SB_STRIDE + ns*8)*2u;
        cpasync16(sB_u + offb, srcb);
    }
    asm volatile("cp.async.commit_group;");
}

__global__ __launch_bounds__(256) void k_gemm_h(float* __restrict__ out){
    extern __shared__ __half smem[];
    __half* sA = smem;
    __half* sB = smem + 2*SA_STAGE;

    int n  = blockIdx.z;
    int bm = blockIdx.y * 128;
    int bn = blockIdx.x * 128;
    const __half* An = g_xh + ((size_t)n << 20);
    const __half* Bn = g_wh + ((size_t)n << 20);

    int tid  = threadIdx.x;
    int lane = tid & 31;
    int warp = tid >> 5;
    int wm = (warp >> 1) * 32;
    int wn = (warp & 1) * 64;

    uint32_t sA_u = (uint32_t)__cvta_generic_to_shared(sA);
    uint32_t sB_u = (uint32_t)__cvta_generic_to_shared(sB);

    float c[2][8][4];
    #pragma unroll
    for (int mt=0;mt<2;mt++)
        #pragma unroll
        for (int nt=0;nt<8;nt++)
            #pragma unroll
            for (int q=0;q<4;q++) c[mt][nt][q] = 0.f;

    gemm_load_stage(An, Bn, sA_u, sB_u, bm, bn, 0, 0, tid);

    for (int it=0; it<32; it++){
        int st = it & 1;
        if (it+1 < 32){
            gemm_load_stage(An, Bn, sA_u, sB_u, bm, bn, (it+1)*32, st^1, tid);
            asm volatile("cp.async.wait_group 1;");
        } else {
            asm volatile("cp.async.wait_group 0;");
        }
        __syncthreads();

        #pragma unroll
        for (int kk=0; kk<32; kk+=16){
            uint32_t ah[2][4], bf[8][2];
            #pragma unroll
            for (int mt=0; mt<2; mt++){
                int row = wm + mt*16 + (lane & 15);
                int col = kk + ((lane >> 4) << 3);
                uint32_t off = (uint32_t)(st*SA_STAGE + row*SA_STRIDE + col)*2u;
                ldsm_x4(ah[mt], sA_u + off);
            }
            #pragma unroll
            for (int nt=0; nt<8; nt++){
                int krow = kk + (lane & 15);
                uint32_t off = (uint32_t)(st*SB_STAGE + krow*SB_STRIDE + wn + nt*8)*2u;
                ldsm_x2t(bf[nt], sB_u + off);
            }
            #pragma unroll
            for (int mt=0;mt<2;mt++)
                #pragma unroll
                for (int nt=0;nt<8;nt++)
                    mma16816(c[mt][nt], ah[mt], bf[nt]);
        }
        __syncthreads();
    }

    // epilogue: scale by s2 and store
    float alpha = fdec(g_minenc), beta = fdec(g_maxenc);
    float s2 = ((beta - alpha)/3.0f/5.0f)/17.0f;
    #pragma unroll
    for (int mt=0;mt<2;mt++){
        int r0 = bm + wm + mt*16 + (lane >> 2);
        #pragma unroll
        for (int nt=0;nt<8;nt++){
            int cb = bn + wn + nt*8 + (lane & 3)*2;
            float2 v0 = make_float2(c[mt][nt][0]*s2, c[mt][nt][1]*s2);
            float2 v1 = make_float2(c[mt][nt][2]*s2, c[mt][nt][3]*s2);
            *reinterpret_cast<float2*>(out + (size_t)r0*8192 + n*1024 + cb)       = v0;
            *reinterpret_cast<float2*>(out + (size_t)(r0+8)*8192 + n*1024 + cb)   = v1;
        }
    }
}

// ---------------- launch ----------------
extern "C" void kernel_launch(void* const* d_in, const int* in_sizes, int n_in,
                              void* d_out, int out_size) {
    const float* x     = (const float*)d_in[0];   // [1024, 8, 1024]
    const float* U     = (const float*)d_in[1];   // [8, 1048576]
    const float* thres = (const float*)d_in[2];   // [1]
    float* out = (float*)d_out;                   // [1024, 8, 1024]

    cudaFuncSetAttribute(k_gemm_h, cudaFuncAttributeMaxDynamicSharedMemorySize, SMEM_BYTES);

    k_init<<<1,1>>>();
    k_minmax<<<512,256>>>(U);
    k_split<<<2048,1024>>>(x);
    k_pass1<<<PBLK,256>>>(U);
    k_scalar<<<1,1024>>>(thres, 0);
    k_pass2<<<PBLK,256>>>(U);
    k_scalar<<<1,1024>>>(thres, 1);
    k_final<<<4096,256>>>(U);
    k_gemm_h<<<dim3(8, 8, 8), 256, SMEM_BYTES>>>(out);
}

// round 5
// speedup vs baseline: 2.6349x; 1.0403x over previous
#include <cuda_runtime.h>
#include <cuda_fp16.h>
#include <math.h>
#include <stdint.h>

#define NROWS 8
#define DTOT  (1u<<20)      // 1048576 columns of U
#define PMAX  2048          // max pass-kernel blocks

// ---------------- static device scratch (allocation-free rule) ----------------
__device__ __half   g_wh[NROWS*DTOT];        // 16 MB: Q [n][d][l] (exact small int in fp16)
__device__ __half   g_xh[NROWS*DTOT];        // 16 MB: x hi half, [n][b][d]
__device__ float    g_part[8*PMAX];          // partials laid out [q][blk]
__device__ unsigned g_minenc, g_maxenc;      // encoded min/max of U
__device__ float    g_coefs[2][8];           // grad_g[gid[i]] per sorted row, per iteration
__device__ float    g_cnts[2][8];            // counts[gid[i]] per sorted row
__device__ int      g_sames[2][7];           // 1 if sorted rows i,i+1 in same group

// ---------------- helpers ----------------
__device__ __forceinline__ unsigned fenc(float f){
    unsigned u = __float_as_uint(f);
    return (u & 0x80000000u) ? ~u : (u | 0x80000000u);
}
__device__ __forceinline__ float fdec(unsigned u){
    unsigned v = (u & 0x80000000u) ? (u & 0x7fffffffu) : ~u;
    return __uint_as_float(v);
}

// values-only compare-exchange
__device__ __forceinline__ void cev(float &a, float &b){
    float lo = fminf(a,b), hi = fmaxf(a,b);
    a = lo; b = hi;
}
__device__ __forceinline__ void sortv8(float v[8]){
    cev(v[0],v[1]); cev(v[2],v[3]); cev(v[4],v[5]); cev(v[6],v[7]);
    cev(v[0],v[2]); cev(v[1],v[3]); cev(v[4],v[6]); cev(v[5],v[7]);
    cev(v[1],v[2]); cev(v[5],v[6]);
    cev(v[0],v[4]); cev(v[1],v[5]); cev(v[2],v[6]); cev(v[3],v[7]);
    cev(v[2],v[4]); cev(v[3],v[5]);
    cev(v[1],v[2]); cev(v[3],v[4]); cev(v[5],v[6]);
}
// stable (value,id) sort carrying one float payload
__device__ __forceinline__ void ce3(float &va, int &ia, float &pa, float &vb, int &ib, float &pb){
    bool sw = (va > vb) || (va == vb && ia > ib);
    if (sw){ float tv=va; va=vb; vb=tv; int ti=ia; ia=ib; ib=ti; float tp=pa; pa=pb; pb=tp; }
}
__device__ __forceinline__ void sort8p(float v[8], int id[8], float p[8]){
    ce3(v[0],id[0],p[0],v[1],id[1],p[1]); ce3(v[2],id[2],p[2],v[3],id[3],p[3]); ce3(v[4],id[4],p[4],v[5],id[5],p[5]); ce3(v[6],id[6],p[6],v[7],id[7],p[7]);
    ce3(v[0],id[0],p[0],v[2],id[2],p[2]); ce3(v[1],id[1],p[1],v[3],id[3],p[3]); ce3(v[4],id[4],p[4],v[6],id[6],p[6]); ce3(v[5],id[5],p[5],v[7],id[7],p[7]);
    ce3(v[1],id[1],p[1],v[2],id[2],p[2]); ce3(v[5],id[5],p[5],v[6],id[6],p[6]);
    ce3(v[0],id[0],p[0],v[4],id[4],p[4]); ce3(v[1],id[1],p[1],v[5],id[5],p[5]); ce3(v[2],id[2],p[2],v[6],id[6],p[6]); ce3(v[3],id[3],p[3],v[7],id[7],p[7]);
    ce3(v[2],id[2],p[2],v[4],id[4],p[4]); ce3(v[3],id[3],p[3],v[5],id[5],p[5]);
    ce3(v[1],id[1],p[1],v[2],id[2],p[2]); ce3(v[3],id[3],p[3],v[4],id[4],p[4]); ce3(v[5],id[5],p[5],v[6],id[6],p[6]);
}

// group totals via prefix/select using global same flags
__device__ __forceinline__ void group_totals_g(const float v[8], const int* sameg, float gt[8]){
    int same[7];
    #pragma unroll
    for (int i=0;i<7;i++) same[i] = sameg[i];
    float gs[8];
    gs[0] = v[0];
    #pragma unroll
    for (int i=1;i<8;i++) gs[i] = v[i] + (same[i-1] ? gs[i-1] : 0.f);
    gt[7] = gs[7];
    #pragma unroll
    for (int i=6;i>=0;i--) gt[i] = same[i] ? gt[i+1] : gs[i];
}

// per-thread accumulated d[8] (7 sums + 1 max) -> block reduce -> g_part[q*PMAX+blk]
__device__ __forceinline__ void delta_reduce(float d[8], int tid, int blk){
    #pragma unroll
    for (int off=16; off; off>>=1){
        #pragma unroll
        for (int q=0;q<7;q++) d[q] += __shfl_xor_sync(0xffffffffu, d[q], off);
        d[7] = fmaxf(d[7], __shfl_xor_sync(0xffffffffu, d[7], off));
    }
    __shared__ float sw[8][8];
    int w = tid>>5;
    if ((tid&31)==0){
        #pragma unroll
        for (int q=0;q<8;q++) sw[w][q]=d[q];
    }
    __syncthreads();
    if (tid < 8){
        int q = tid;
        float a = sw[0][q];
        if (q==7){
            #pragma unroll
            for (int w2=1;w2<8;w2++) a = fmaxf(a, sw[w2][q]);
        } else {
            #pragma unroll
            for (int w2=1;w2<8;w2++) a += sw[w2][q];
        }
        g_part[q*PMAX + blk] = a;
    }
}

// ---------------- fused prep: split (blocks 0..2047) + minmax (blocks 2048..2559) --------
__global__ void k_init(){
    g_minenc = 0xFFFFFFFFu;
    g_maxenc = 0u;
}

__global__ __launch_bounds__(1024) void k_prep(const float* __restrict__ x, const float* __restrict__ U){
    int blk = blockIdx.x;
    if (blk < 2048){
        // split: x [b][n][d] fp32 -> g_xh [n][b][d] fp16, 4 elems/thread
        unsigned idx = (unsigned)blk*1024u + threadIdx.x;
        unsigned base = idx*4u;
        unsigned d = base & 1023u;
        unsigned n = (base >> 10) & 7u;
        unsigned b = base >> 13;
        float4 xv = *reinterpret_cast<const float4*>(x + base);
        __half2 h0 = __floats2half2_rn(xv.x, xv.y);
        __half2 h1 = __floats2half2_rn(xv.z, xv.w);
        unsigned j = (n << 20) | (b << 10) | d;
        *reinterpret_cast<__half2*>(g_xh + j)     = h0;
        *reinterpret_cast<__half2*>(g_xh + j + 2) = h1;
    } else {
        int tid = threadIdx.x;
        unsigned t = (unsigned)(blk-2048)*1024u + tid;   // 0..524287
        const float4* U4 = reinterpret_cast<const float4*>(U);
        float lo =  INFINITY, hi = -INFINITY;
        #pragma unroll
        for (int i=0;i<4;i++){
            float4 u = U4[t + (unsigned)i*524288u];
            lo = fminf(lo, fminf(fminf(u.x,u.y), fminf(u.z,u.w)));
            hi = fmaxf(hi, fmaxf(fmaxf(u.x,u.y), fmaxf(u.z,u.w)));
        }
        #pragma unroll
        for (int off=16; off; off>>=1){
            lo = fminf(lo, __shfl_xor_sync(0xffffffffu, lo, off));
            hi = fmaxf(hi, __shfl_xor_sync(0xffffffffu, hi, off));
        }
        __shared__ float slo[32], shi[32];
        if ((tid&31)==0){ slo[tid>>5]=lo; shi[tid>>5]=hi; }
        __syncthreads();
        if (tid==0){
            #pragma unroll
            for (int w=1;w<32;w++){ lo=fminf(lo,slo[w]); hi=fmaxf(hi,shi[w]); }
            atomicMin(&g_minenc, fenc(lo));
            atomicMax(&g_maxenc, fenc(hi));
        }
    }
}

// ---------------- pass 1: 4 cols/thread via float4 ----------------
__global__ __launch_bounds__(256) void k_pass1(const float* __restrict__ U){
    int tid = threadIdx.x;
    unsigned c4 = (unsigned)blockIdx.x*256u + tid;   // float4 index within a row
    float alpha = fdec(g_minenc), beta = fdec(g_maxenc);
    float s0 = (beta - alpha) / 3.0f;
    float v[4][8];
    #pragma unroll
    for (int r=0;r<8;r++){
        float4 u = reinterpret_cast<const float4*>(U)[((size_t)r<<18) + c4];
        v[0][r] = u.x - s0*floorf(u.x/s0);
        v[1][r] = u.y - s0*floorf(u.y/s0);
        v[2][r] = u.z - s0*floorf(u.z/s0);
        v[3][r] = u.w - s0*floorf(u.w/s0);
    }
    float d[8];
    #pragma unroll
    for (int q=0;q<8;q++) d[q]=0.f;
    #pragma unroll
    for (int cc=0;cc<4;cc++){
        sortv8(v[cc]);
        #pragma unroll
        for (int q=0;q<7;q++){
            float dd = v[cc][q+1]-v[cc][q];
            d[q] += dd;
            d[7] = fmaxf(d[7], dd);
        }
    }
    delta_reduce(d, tid, blockIdx.x);
}

// ---------------- scalar reduce + grouping ----------------
__global__ void k_scalar(const float* __restrict__ thres, int set, int nblk){
    int tid = threadIdx.x;        // 1024
    int q = tid >> 7;
    int r = tid & 127;
    float a = 0.f;
    for (int p=r; p<nblk; p+=128){
        float xv = g_part[q*PMAX + p];
        a = (q==7) ? fmaxf(a,xv) : (a+xv);
    }
    #pragma unroll
    for (int off=16; off; off>>=1){
        float b = __shfl_xor_sync(0xffffffffu, a, off);
        a = (q==7) ? fmaxf(a,b) : (a+b);
    }
    __shared__ float s4[8][4];
    __shared__ float sred[8];
    if ((tid&31)==0) s4[q][(tid>>5)&3] = a;
    __syncthreads();
    if (tid < 8){
        float x0=s4[tid][0], x1=s4[tid][1], x2=s4[tid][2], x3=s4[tid][3];
        sred[tid] = (tid==7) ? fmaxf(fmaxf(x0,x1),fmaxf(x2,x3)) : ((x0+x1)+(x2+x3));
    }
    __syncthreads();
    if (tid==0){
        float dmax = sred[7];
        float sigt = 1.0f/(1.0f + expf(-thres[0]));
        float sp[7], bv[7];
        int gid[8]; gid[0]=0;
        for (int i=0;i<7;i++){
            float mean = (sred[i]/dmax) * (1.0f/1048576.0f);
            float z = (mean - sigt)/0.01f;
            sp[i] = 1.0f/(1.0f + expf(-z));
            bv[i] = rintf(sp[i]);
            gid[i+1] = gid[i] + (int)bv[i];
        }
        int counts[8]; float glog[8];
        for (int g=0;g<8;g++){ counts[g]=0; glog[g]=0.f; }
        for (int rr=0;rr<8;rr++) counts[gid[rr]]++;
        for (int i=0;i<7;i++) glog[gid[i]] += logf(bv[i]==1.0f ? sp[i] : 1.0f - sp[i]);
        float gg[8];
        for (int g=0;g<8;g++) gg[g] = expf(glog[g]);
        for (int rr=0;rr<8;rr++){ g_coefs[set][rr] = gg[gid[rr]]; g_cnts[set][rr] = (float)counts[gid[rr]]; }
        for (int i=0;i<7;i++) g_sames[set][i] = (bv[i]==0.0f) ? 1 : 0;
    }
}

// ---------------- pass 2: 2 cols/thread via float2 ----------------
__device__ __forceinline__ void pass2_col(const float u[8], float s0, float s1, float nv[8]){
    float v[8], p[8]; int id[8];
    #pragma unroll
    for (int r=0;r<8;r++){
        v[r] = u[r] - s0*floorf(u[r]/s0);
        id[r] = r;
        p[r] = u[r];
    }
    sort8p(v, id, p);
    float gt[8];
    group_totals_g(v, g_sames[0], gt);
    #pragma unroll
    for (int i=0;i<8;i++){
        float mean = gt[i]/g_cnts[0][i];
        float t    = g_coefs[0][i]*mean;
        float add  = s1*floorf(t/s1);
        float f0   = floorf(p[i]/s0);
        float v0   = s0*f0;
        float vals1 = v0 + add;
        nv[i] = p[i] - vals1;
    }
    sortv8(nv);
}

__global__ __launch_bounds__(256) void k_pass2(const float* __restrict__ U){
    int tid = threadIdx.x;
    unsigned c2 = (unsigned)blockIdx.x*256u + tid;   // float2 index
    float alpha = fdec(g_minenc), beta = fdec(g_maxenc);
    float s0 = (beta - alpha)/3.0f;
    float s1 = s0/5.0f;
    float ua[8], ub[8];
    #pragma unroll
    for (int r=0;r<8;r++){
        float2 u = reinterpret_cast<const float2*>(U)[((size_t)r<<19) + c2];
        ua[r]=u.x; ub[r]=u.y;
    }
    float na[8], nb[8];
    pass2_col(ua, s0, s1, na);
    pass2_col(ub, s0, s1, nb);
    float d[8];
    #pragma unroll
    for (int q=0;q<7;q++){
        float da = na[q+1]-na[q];
        float db = nb[q+1]-nb[q];
        d[q] = da + db;
    }
    d[7] = 0.f;
    #pragma unroll
    for (int q=0;q<7;q++) d[7] = fmaxf(d[7], fmaxf(na[q+1]-na[q], nb[q+1]-nb[q]));
    delta_reduce(d, tid, blockIdx.x);
}

// ---------------- final: 2 cols/thread, permutation inverted, coalesced half2 stores ----
__device__ __forceinline__ void final_col(const float u[8], float s0, float s1, float s2, float Qr[8]){
    float v[8], p[8]; int id[8];
    #pragma unroll
    for (int r=0;r<8;r++){
        v[r] = u[r] - s0*floorf(u[r]/s0);
        id[r] = r;
        p[r] = u[r];
    }
    sort8p(v, id, p);
    float gt[8];
    group_totals_g(v, g_sames[0], gt);
    float nv[8], pay[8]; int nid[8];
    #pragma unroll
    for (int i=0;i<8;i++){
        float mean = gt[i]/g_cnts[0][i];
        float t    = g_coefs[0][i]*mean;
        float f1f  = floorf(t/s1);
        float add  = s1*f1f;
        float f0f  = floorf(p[i]/s0);
        float v0   = s0*f0f;
        float vals1 = v0 + add;
        nv[i]  = p[i] - vals1;
        nid[i] = id[i];
        pay[i] = 85.0f*f0f + 17.0f*f1f;   // exact small integer
    }
    sort8p(nv, nid, pay);
    float gt2[8];
    group_totals_g(nv, g_sames[1], gt2);
    float Q[8];
    #pragma unroll
    for (int j=0;j<8;j++){
        float mean = gt2[j]/g_cnts[1][j];
        float t    = g_coefs[1][j]*mean;
        float f2f  = floorf(t/s2);
        Q[j] = pay[j] + f2f;              // |Q| < 512 -> exact in fp16
    }
    // invert permutation in registers (64 predicated selects)
    #pragma unroll
    for (int r=0;r<8;r++){
        float q = 0.f;
        #pragma unroll
        for (int j=0;j<8;j++) q = (nid[j]==r) ? Q[j] : q;
        Qr[r] = q;
    }
}

__global__ __launch_bounds__(256) void k_final(const float* __restrict__ U){
    int tid = threadIdx.x;
    unsigned c2 = (unsigned)blockIdx.x*256u + tid;   // float2 column-pair index
    float alpha = fdec(g_minenc), beta = fdec(g_maxenc);
    float s0 = (beta - alpha)/3.0f;
    float s1 = s0/5.0f;
    float s2 = s1/17.0f;
    float ua[8], ub[8];
    #pragma unroll
    for (int r=0;r<8;r++){
        float2 u = reinterpret_cast<const float2*>(U)[((size_t)r<<19) + c2];
        ua[r]=u.x; ub[r]=u.y;
    }
    float Qa[8], Qb[8];
    final_col(ua, s0, s1, s2, Qa);
    final_col(ub, s0, s1, s2, Qb);
    #pragma unroll
    for (int r=0;r<8;r++){
        __half2 h = __floats2half2_rn(Qa[r], Qb[r]);
        reinterpret_cast<__half2*>(g_wh)[((size_t)r<<19) + c2] = h;
    }
}

// ---------------- fp16 mma.sync GEMM (hi-only) ----------------
#define SA_STRIDE 40
#define SB_STRIDE 136
#define SA_STAGE  (128*SA_STRIDE)
#define SB_STAGE  (32*SB_STRIDE)
#define SMEM_HALFS (2*SA_STAGE + 2*SB_STAGE)
#define SMEM_BYTES (SMEM_HALFS*2)

__device__ __forceinline__ void ldsm_x4(uint32_t r[4], uint32_t addr){
    asm volatile("ldmatrix.sync.aligned.m8n8.x4.shared.b16 {%0,%1,%2,%3}, [%4];"
        : "=r"(r[0]),"=r"(r[1]),"=r"(r[2]),"=r"(r[3]) : "r"(addr));
}
__device__ __forceinline__ void ldsm_x2t(uint32_t r[2], uint32_t addr){
    asm volatile("ldmatrix.sync.aligned.m8n8.x2.trans.shared.b16 {%0,%1}, [%2];"
        : "=r"(r[0]),"=r"(r[1]) : "r"(addr));
}
__device__ __forceinline__ void mma16816(float c[4], const uint32_t a[4], const uint32_t b[2]){
    asm volatile("mma.sync.aligned.m16n8k16.row.col.f32.f16.f16.f32 "
        "{%0,%1,%2,%3}, {%4,%5,%6,%7}, {%8,%9}, {%0,%1,%2,%3};"
        : "+f"(c[0]),"+f"(c[1]),"+f"(c[2]),"+f"(c[3])
        : "r"(a[0]),"r"(a[1]),"r"(a[2]),"r"(a[3]), "r"(b[0]),"r"(b[1]));
}
__device__ __forceinline__ void cpasync16(uint32_t dst, const void* src){
    asm volatile("cp.async.cg.shared.global [%0], [%1], 16;" :: "r"(dst), "l"(src));
}

__device__ __forceinline__ void gemm_load_stage(
    const __half* Ah, const __half* Bn,
    uint32_t sA_u, uint32_t sB_u,
    int bm, int bn, int k0, int st, int tid)
{
    #pragma unroll
    for (int i=0;i<2;i++){
        int ch = tid + i*256;
        int r  = ch >> 2, sg = ch & 3;
        const __half* srch = Ah + (size_t)(bm+r)*1024 + k0 + sg*8;
        uint32_t off = (uint32_t)(st*SA_STAGE + r*SA_STRIDE + sg*8)*2u;
        cpasync16(sA_u + off, srch);
        int kr = ch >> 4, ns = ch & 15;
        const __half* srcb = Bn + (size_t)(k0+kr)*1024 + bn + ns*8;
        uint32_t offb = (uint32_t)(st*SB_STAGE + kr*SB_STRIDE + ns*8)*2u;
        cpasync16(sB_u + offb, srcb);
    }
    asm volatile("cp.async.commit_group;");
}

__global__ __launch_bounds__(256) void k_gemm_h(float* __restrict__ out){
    extern __shared__ __half smem[];
    __half* sA = smem;
    __half* sB = smem + 2*SA_STAGE;

    int n  = blockIdx.z;
    int bm = blockIdx.y * 128;
    int bn = blockIdx.x * 128;
    const __half* An = g_xh + ((size_t)n << 20);
    const __half* Bn = g_wh + ((size_t)n << 20);

    int tid  = threadIdx.x;
    int lane = tid & 31;
    int warp = tid >> 5;
    int wm = (warp >> 1) * 32;
    int wn = (warp & 1) * 64;

    uint32_t sA_u = (uint32_t)__cvta_generic_to_shared(sA);
    uint32_t sB_u = (uint32_t)__cvta_generic_to_shared(sB);

    float c[2][8][4];
    #pragma unroll
    for (int mt=0;mt<2;mt++)
        #pragma unroll
        for (int nt=0;nt<8;nt++)
            #pragma unroll
            for (int q=0;q<4;q++) c[mt][nt][q] = 0.f;

    gemm_load_stage(An, Bn, sA_u, sB_u, bm, bn, 0, 0, tid);

    for (int it=0; it<32; it++){
        int st = it & 1;
        if (it+1 < 32){
            gemm_load_stage(An, Bn, sA_u, sB_u, bm, bn, (it+1)*32, st^1, tid);
            asm volatile("cp.async.wait_group 1;");
        } else {
            asm volatile("cp.async.wait_group 0;");
        }
        __syncthreads();

        #pragma unroll
        for (int kk=0; kk<32; kk+=16){
            uint32_t ah[2][4], bf[8][2];
            #pragma unroll
            for (int mt=0; mt<2; mt++){
                int row = wm + mt*16 + (lane & 15);
                int col = kk + ((lane >> 4) << 3);
                uint32_t off = (uint32_t)(st*SA_STAGE + row*SA_STRIDE + col)*2u;
                ldsm_x4(ah[mt], sA_u + off);
            }
            #pragma unroll
            for (int nt=0; nt<8; nt++){
                int krow = kk + (lane & 15);
                uint32_t off = (uint32_t)(st*SB_STAGE + krow*SB_STRIDE + wn + nt*8)*2u;
                ldsm_x2t(bf[nt], sB_u + off);
            }
            #pragma unroll
            for (int mt=0;mt<2;mt++)
                #pragma unroll
                for (int nt=0;nt<8;nt++)
                    mma16816(c[mt][nt], ah[mt], bf[nt]);
        }
        __syncthreads();
    }

    float alpha = fdec(g_minenc), beta = fdec(g_maxenc);
    float s2 = ((beta - alpha)/3.0f/5.0f)/17.0f;
    #pragma unroll
    for (int mt=0;mt<2;mt++){
        int r0 = bm + wm + mt*16 + (lane >> 2);
        #pragma unroll
        for (int nt=0;nt<8;nt++){
            int cb = bn + wn + nt*8 + (lane & 3)*2;
            float2 v0 = make_float2(c[mt][nt][0]*s2, c[mt][nt][1]*s2);
            float2 v1 = make_float2(c[mt][nt][2]*s2, c[mt][nt][3]*s2);
            *reinterpret_cast<float2*>(out + (size_t)r0*8192 + n*1024 + cb)       = v0;
            *reinterpret_cast<float2*>(out + (size_t)(r0+8)*8192 + n*1024 + cb)   = v1;
        }
    }
}

// ---------------- launch ----------------
extern "C" void kernel_launch(void* const* d_in, const int* in_sizes, int n_in,
                              void* d_out, int out_size) {
    const float* x     = (const float*)d_in[0];   // [1024, 8, 1024]
    const float* U     = (const float*)d_in[1];   // [8, 1048576]
    const float* thres = (const float*)d_in[2];   // [1]
    float* out = (float*)d_out;                   // [1024, 8, 1024]

    cudaFuncSetAttribute(k_gemm_h, cudaFuncAttributeMaxDynamicSharedMemorySize, SMEM_BYTES);

    k_init<<<1,1>>>();
    k_prep<<<2560,1024>>>(x, U);        // fused split + minmax
    k_pass1<<<1024,256>>>(U);           // 4 cols/thread
    k_scalar<<<1,1024>>>(thres, 0, 1024);
    k_pass2<<<2048,256>>>(U);           // 2 cols/thread
    k_scalar<<<1,1024>>>(thres, 1, 2048);
    k_final<<<2048,256>>>(U);           // 2 cols/thread, coalesced writes
    k_gemm_h<<<dim3(8, 8, 8), 256, SMEM_BYTES>>>(out);
}